// round 3
// baseline (speedup 1.0000x reference)
#include <cuda_runtime.h>
#include <stdint.h>
#include <math.h>

#define BB 2
#define SS 2048
#define DD 1024
#define HH 16
#define NR (BB*SS)            // 4096 rows
#define ATT_SCALE 0.125f      // 1/sqrt(64)

// ---------------- device scratch (no cudaMalloc allowed) ----------------
static __device__ float g_W3[3 * DD * DD];          // concat(Wq,Wk,Wv) rows
static __device__ float g_b3[3 * DD];
static __device__ float g_QKV[(size_t)NR * 3 * DD]; // (4096, 3072): Q|K|V
static __device__ float g_C[(size_t)NR * DD];       // ctx (B,S,D)

// ---------------- tf32 helpers ----------------
__device__ __forceinline__ uint32_t f2t(float x) {
    uint32_t r;
    asm("cvt.rna.tf32.f32 %0, %1;" : "=r"(r) : "f"(x));
    return r;
}
__device__ __forceinline__ void mma8(float* c, const uint32_t* a, const uint32_t* b) {
    asm volatile(
        "mma.sync.aligned.m16n8k8.row.col.f32.tf32.tf32.f32 "
        "{%0,%1,%2,%3},{%4,%5,%6,%7},{%8,%9},{%0,%1,%2,%3};"
        : "+f"(c[0]), "+f"(c[1]), "+f"(c[2]), "+f"(c[3])
        : "r"(a[0]), "r"(a[1]), "r"(a[2]), "r"(a[3]), "r"(b[0]), "r"(b[1]));
}

// ---------------- weight concat ----------------
__global__ void concat_kernel(const float* __restrict__ Wq, const float* __restrict__ Wk,
                              const float* __restrict__ Wv, const float* __restrict__ bq,
                              const float* __restrict__ bk, const float* __restrict__ bv) {
    int i = blockIdx.x * 256 + threadIdx.x;
    if (i < DD * DD) {
        g_W3[i]               = Wq[i];
        g_W3[DD * DD + i]     = Wk[i];
        g_W3[2 * DD * DD + i] = Wv[i];
    }
    if (i < DD) {
        g_b3[i]          = bq[i];
        g_b3[DD + i]     = bk[i];
        g_b3[2 * DD + i] = bv[i];
    }
}

// ---------------- NT GEMM (tf32 tensor): C[M,N] = A[M,K] @ B[N,K]^T + bias ----
__global__ __launch_bounds__(256) void gemm_nt_tf32(
    const float* __restrict__ A, const float* __restrict__ Bw,
    const float* __restrict__ bias, float* __restrict__ C,
    int M, int N, int K)
{
    __shared__ uint32_t As[2][128][20];
    __shared__ uint32_t Bs[2][128][20];

    const int t    = threadIdx.x;
    const int lane = t & 31, w = t >> 5;
    const int g    = lane >> 2, tg = lane & 3;
    const int wm   = w & 3, wn = w >> 2;
    const int row0 = blockIdx.y * 128;
    const int col0 = blockIdx.x * 128;

    const int srow = t >> 1;            // 0..127
    const int skq  = (t & 1) * 8;       // 0 or 8
    const float* Ap = A  + (size_t)(row0 + srow) * K + skq;
    const float* Bp = Bw + (size_t)(col0 + srow) * K + skq;

    float acc[2][8][4];
#pragma unroll
    for (int i = 0; i < 2; i++)
#pragma unroll
        for (int j = 0; j < 8; j++)
#pragma unroll
            for (int q = 0; q < 4; q++) acc[i][j][q] = 0.f;

    float4 ra0, ra1, rb0, rb1;
    ra0 = *(const float4*)(Ap);     ra1 = *(const float4*)(Ap + 4);
    rb0 = *(const float4*)(Bp);     rb1 = *(const float4*)(Bp + 4);
    *(uint4*)&As[0][srow][skq]     = make_uint4(f2t(ra0.x), f2t(ra0.y), f2t(ra0.z), f2t(ra0.w));
    *(uint4*)&As[0][srow][skq + 4] = make_uint4(f2t(ra1.x), f2t(ra1.y), f2t(ra1.z), f2t(ra1.w));
    *(uint4*)&Bs[0][srow][skq]     = make_uint4(f2t(rb0.x), f2t(rb0.y), f2t(rb0.z), f2t(rb0.w));
    *(uint4*)&Bs[0][srow][skq + 4] = make_uint4(f2t(rb1.x), f2t(rb1.y), f2t(rb1.z), f2t(rb1.w));
    __syncthreads();

    const int nk = K / 16;
    for (int kc = 0; kc < nk; kc++) {
        const int p = kc & 1;
        if (kc + 1 < nk) {
            const float* Ap2 = Ap + (size_t)(kc + 1) * 16;
            const float* Bp2 = Bp + (size_t)(kc + 1) * 16;
            ra0 = *(const float4*)(Ap2);  ra1 = *(const float4*)(Ap2 + 4);
            rb0 = *(const float4*)(Bp2);  rb1 = *(const float4*)(Bp2 + 4);
        }
#pragma unroll
        for (int ks = 0; ks < 16; ks += 8) {
            uint32_t af[2][4], bf[8][2];
#pragma unroll
            for (int mt = 0; mt < 2; mt++) {
                const int r = wm * 32 + mt * 16 + g;
                af[mt][0] = As[p][r][ks + tg];
                af[mt][1] = As[p][r + 8][ks + tg];
                af[mt][2] = As[p][r][ks + tg + 4];
                af[mt][3] = As[p][r + 8][ks + tg + 4];
            }
#pragma unroll
            for (int nt = 0; nt < 8; nt++) {
                const int n = wn * 64 + nt * 8 + g;
                bf[nt][0] = Bs[p][n][ks + tg];
                bf[nt][1] = Bs[p][n][ks + tg + 4];
            }
#pragma unroll
            for (int mt = 0; mt < 2; mt++)
#pragma unroll
                for (int nt = 0; nt < 8; nt++)
                    mma8(acc[mt][nt], af[mt], bf[nt]);
        }
        if (kc + 1 < nk) {
            const int q = (kc + 1) & 1;
            *(uint4*)&As[q][srow][skq]     = make_uint4(f2t(ra0.x), f2t(ra0.y), f2t(ra0.z), f2t(ra0.w));
            *(uint4*)&As[q][srow][skq + 4] = make_uint4(f2t(ra1.x), f2t(ra1.y), f2t(ra1.z), f2t(ra1.w));
            *(uint4*)&Bs[q][srow][skq]     = make_uint4(f2t(rb0.x), f2t(rb0.y), f2t(rb0.z), f2t(rb0.w));
            *(uint4*)&Bs[q][srow][skq + 4] = make_uint4(f2t(rb1.x), f2t(rb1.y), f2t(rb1.z), f2t(rb1.w));
        }
        __syncthreads();
    }

#pragma unroll
    for (int mt = 0; mt < 2; mt++) {
        const int r = row0 + wm * 32 + mt * 16 + g;
#pragma unroll
        for (int nt = 0; nt < 8; nt++) {
            const int cc = col0 + wn * 64 + nt * 8 + 2 * tg;
            float2 v0, v1;
            v0.x = acc[mt][nt][0] + bias[cc];
            v0.y = acc[mt][nt][1] + bias[cc + 1];
            v1.x = acc[mt][nt][2] + bias[cc];
            v1.y = acc[mt][nt][3] + bias[cc + 1];
            *(float2*)(C + (size_t)r * N + cc)       = v0;
            *(float2*)(C + (size_t)(r + 8) * N + cc) = v1;
        }
    }
}

// ---------------- fused attention: scores + softmax + ctx, two-pass flash ----------
// Block = one 64-row q-tile of one (b,h). Dynamic smem layout below.
#define SM_Q 0
#define SM_K 17408
#define SM_V 34816
#define SM_P 53248
#define SM_RED 70656
#define SM_TOTAL 72192

__global__ __launch_bounds__(256) void fused_attn(
    const float* __restrict__ QKV, float* __restrict__ attn, float* __restrict__ Cout)
{
    extern __shared__ char smraw[];
    uint32_t (*Qs)[68] = (uint32_t(*)[68])(smraw + SM_Q);
    uint32_t (*Ks)[68] = (uint32_t(*)[68])(smraw + SM_K);
    uint32_t (*Vs)[72] = (uint32_t(*)[72])(smraw + SM_V);
    uint32_t (*Ps)[68] = (uint32_t(*)[68])(smraw + SM_P);
    float* red_m = (float*)(smraw + SM_RED);   // [2][64]
    float* red_l = red_m + 128;                // [2][64]
    float* m_run = red_l + 128;                // [64]
    float* l_run = m_run + 64;                 // [64] (becomes 1/l)

    const int qt = blockIdx.x, z = blockIdx.y;
    const int b = z >> 4, h = z & 15;
    const int t = threadIdx.x, lane = t & 31, w = t >> 5;
    const int g = lane >> 2, tg = lane & 3;
    const int wm = w & 3, wn = w >> 2;

    const float* Qb = QKV + ((size_t)(b * SS) + qt * 64) * 3072 + h * 64;
    const float* Kb = QKV + (size_t)(b * SS) * 3072 + DD + h * 64;
    const float* Vb = QKV + (size_t)(b * SS) * 3072 + 2 * DD + h * 64;

    const int sr = t >> 2, sc = (t & 3) * 16;

    // load Q tile (tf32)
#pragma unroll
    for (int i = 0; i < 16; i += 4) {
        float4 v = *(const float4*)(Qb + (size_t)sr * 3072 + sc + i);
        *(uint4*)&Qs[sr][sc + i] = make_uint4(f2t(v.x), f2t(v.y), f2t(v.z), f2t(v.w));
    }
    if (t < 64) { m_run[t] = -1e30f; l_run[t] = 0.f; }

    const int rq0 = qt * 64 + wm * 16 + g;
    const int rq1 = rq0 + 8;
    const int rloc0 = wm * 16 + g, rloc1 = rloc0 + 8;

    // ---------------- pass A: row max & sum ----------------
    for (int kt = 0; kt <= qt; kt++) {
        __syncthreads();
#pragma unroll
        for (int i = 0; i < 16; i += 4) {
            float4 v = *(const float4*)(Kb + (size_t)(kt * 64 + sr) * 3072 + sc + i);
            *(uint4*)&Ks[sr][sc + i] = make_uint4(f2t(v.x), f2t(v.y), f2t(v.z), f2t(v.w));
        }
        __syncthreads();

        float acc[4][4];
#pragma unroll
        for (int nt = 0; nt < 4; nt++)
#pragma unroll
            for (int q = 0; q < 4; q++) acc[nt][q] = 0.f;
#pragma unroll
        for (int ks = 0; ks < 64; ks += 8) {
            uint32_t af[4];
            af[0] = Qs[rloc0][ks + tg];     af[1] = Qs[rloc1][ks + tg];
            af[2] = Qs[rloc0][ks + tg + 4]; af[3] = Qs[rloc1][ks + tg + 4];
#pragma unroll
            for (int nt = 0; nt < 4; nt++) {
                uint32_t bf[2];
                const int n = wn * 32 + nt * 8 + g;
                bf[0] = Ks[n][ks + tg];
                bf[1] = Ks[n][ks + tg + 4];
                mma8(acc[nt], af, bf);
            }
        }

        float sv[4][4];
        float m0 = -1e30f, m1 = -1e30f;
#pragma unroll
        for (int nt = 0; nt < 4; nt++) {
            const int c0 = kt * 64 + wn * 32 + nt * 8 + 2 * tg;
            float s00 = acc[nt][0] * ATT_SCALE, s01 = acc[nt][1] * ATT_SCALE;
            float s10 = acc[nt][2] * ATT_SCALE, s11 = acc[nt][3] * ATT_SCALE;
            if (c0     > rq0) s00 = -1e30f;
            if (c0 + 1 > rq0) s01 = -1e30f;
            if (c0     > rq1) s10 = -1e30f;
            if (c0 + 1 > rq1) s11 = -1e30f;
            sv[nt][0] = s00; sv[nt][1] = s01; sv[nt][2] = s10; sv[nt][3] = s11;
            m0 = fmaxf(m0, fmaxf(s00, s01));
            m1 = fmaxf(m1, fmaxf(s10, s11));
        }
        m0 = fmaxf(m0, __shfl_xor_sync(~0u, m0, 1));
        m0 = fmaxf(m0, __shfl_xor_sync(~0u, m0, 2));
        m1 = fmaxf(m1, __shfl_xor_sync(~0u, m1, 1));
        m1 = fmaxf(m1, __shfl_xor_sync(~0u, m1, 2));
        float l0 = 0.f, l1 = 0.f;
#pragma unroll
        for (int nt = 0; nt < 4; nt++) {
            l0 += (sv[nt][0] > -1e29f) ? __expf(sv[nt][0] - m0) : 0.f;
            l0 += (sv[nt][1] > -1e29f) ? __expf(sv[nt][1] - m0) : 0.f;
            l1 += (sv[nt][2] > -1e29f) ? __expf(sv[nt][2] - m1) : 0.f;
            l1 += (sv[nt][3] > -1e29f) ? __expf(sv[nt][3] - m1) : 0.f;
        }
        l0 += __shfl_xor_sync(~0u, l0, 1); l0 += __shfl_xor_sync(~0u, l0, 2);
        l1 += __shfl_xor_sync(~0u, l1, 1); l1 += __shfl_xor_sync(~0u, l1, 2);
        if (tg == 0) {
            red_m[wn * 64 + rloc0] = m0;  red_l[wn * 64 + rloc0] = l0;
            red_m[wn * 64 + rloc1] = m1;  red_l[wn * 64 + rloc1] = l1;
        }
        __syncthreads();
        if (t < 64) {
            float mA = red_m[t], mB = red_m[64 + t];
            float lA = red_l[t], lB = red_l[64 + t];
            float mt_ = fmaxf(mA, mB);
            float lt_ = ((mA > -1e29f) ? lA * __expf(mA - mt_) : 0.f)
                      + ((mB > -1e29f) ? lB * __expf(mB - mt_) : 0.f);
            float mo = m_run[t];
            float mn = fmaxf(mo, mt_);
            float ln = ((mo  > -1e29f) ? l_run[t] * __expf(mo  - mn) : 0.f)
                     + ((mt_ > -1e29f) ? lt_      * __expf(mt_ - mn) : 0.f);
            m_run[t] = mn; l_run[t] = ln;
        }
    }
    __syncthreads();
    if (t < 64) l_run[t] = 1.0f / l_run[t];   // every causal row has >=1 valid col

    // ---------------- pass B: write probs + accumulate ctx ----------------
    float cacc[4][4];
#pragma unroll
    for (int nt = 0; nt < 4; nt++)
#pragma unroll
        for (int q = 0; q < 4; q++) cacc[nt][q] = 0.f;

    for (int kt = 0; kt <= qt; kt++) {
        __syncthreads();
#pragma unroll
        for (int i = 0; i < 16; i += 4) {
            float4 v = *(const float4*)(Kb + (size_t)(kt * 64 + sr) * 3072 + sc + i);
            *(uint4*)&Ks[sr][sc + i] = make_uint4(f2t(v.x), f2t(v.y), f2t(v.z), f2t(v.w));
            v = *(const float4*)(Vb + (size_t)(kt * 64 + sr) * 3072 + sc + i);
            *(uint4*)&Vs[sr][sc + i] = make_uint4(f2t(v.x), f2t(v.y), f2t(v.z), f2t(v.w));
        }
        __syncthreads();

        float acc[4][4];
#pragma unroll
        for (int nt = 0; nt < 4; nt++)
#pragma unroll
            for (int q = 0; q < 4; q++) acc[nt][q] = 0.f;
#pragma unroll
        for (int ks = 0; ks < 64; ks += 8) {
            uint32_t af[4];
            af[0] = Qs[rloc0][ks + tg];     af[1] = Qs[rloc1][ks + tg];
            af[2] = Qs[rloc0][ks + tg + 4]; af[3] = Qs[rloc1][ks + tg + 4];
#pragma unroll
            for (int nt = 0; nt < 4; nt++) {
                uint32_t bf[2];
                const int n = wn * 32 + nt * 8 + g;
                bf[0] = Ks[n][ks + tg];
                bf[1] = Ks[n][ks + tg + 4];
                mma8(acc[nt], af, bf);
            }
        }

        const float mr0 = m_run[rloc0], il0 = l_run[rloc0];
        const float mr1 = m_run[rloc1], il1 = l_run[rloc1];
#pragma unroll
        for (int nt = 0; nt < 4; nt++) {
            const int c0 = kt * 64 + wn * 32 + nt * 8 + 2 * tg;
            float p00 = (c0     <= rq0) ? __expf(acc[nt][0] * ATT_SCALE - mr0) * il0 : 0.f;
            float p01 = (c0 + 1 <= rq0) ? __expf(acc[nt][1] * ATT_SCALE - mr0) * il0 : 0.f;
            float p10 = (c0     <= rq1) ? __expf(acc[nt][2] * ATT_SCALE - mr1) * il1 : 0.f;
            float p11 = (c0 + 1 <= rq1) ? __expf(acc[nt][3] * ATT_SCALE - mr1) * il1 : 0.f;
            float2 v0; v0.x = p00; v0.y = p01;
            float2 v1; v1.x = p10; v1.y = p11;
            *(float2*)(attn + ((size_t)z * SS + rq0) * SS + c0) = v0;
            *(float2*)(attn + ((size_t)z * SS + rq1) * SS + c0) = v1;
            const int cl = wn * 32 + nt * 8 + 2 * tg;
            Ps[rloc0][cl]     = f2t(p00);
            Ps[rloc0][cl + 1] = f2t(p01);
            Ps[rloc1][cl]     = f2t(p10);
            Ps[rloc1][cl + 1] = f2t(p11);
        }
        __syncthreads();

#pragma unroll
        for (int ks = 0; ks < 64; ks += 8) {
            uint32_t af[4];
            af[0] = Ps[rloc0][ks + tg];     af[1] = Ps[rloc1][ks + tg];
            af[2] = Ps[rloc0][ks + tg + 4]; af[3] = Ps[rloc1][ks + tg + 4];
#pragma unroll
            for (int nt = 0; nt < 4; nt++) {
                uint32_t bf[2];
                const int n = wn * 32 + nt * 8 + g;
                bf[0] = Vs[ks + tg][n];
                bf[1] = Vs[ks + tg + 4][n];
                mma8(cacc[nt], af, bf);
            }
        }
    }

    // ctx epilogue -> g_C (B,S,D)
    const int qrow = qt * 64 + wm * 16 + g;
    const int dcol = h * 64 + wn * 32;
#pragma unroll
    for (int nt = 0; nt < 4; nt++) {
        const int cc = dcol + nt * 8 + 2 * tg;
        float2 v0, v1;
        v0.x = cacc[nt][0]; v0.y = cacc[nt][1];
        v1.x = cacc[nt][2]; v1.y = cacc[nt][3];
        *(float2*)(Cout + ((size_t)(b * SS) + qrow) * DD + cc)     = v0;
        *(float2*)(Cout + ((size_t)(b * SS) + qrow + 8) * DD + cc) = v1;
    }

    // zero-fill strict-upper tiles of this q-tile's attn rows
    const float4 z4 = make_float4(0.f, 0.f, 0.f, 0.f);
    for (int kt = qt + 1; kt < 32; kt++) {
        float* p0 = attn + ((size_t)z * SS + qt * 64 + sr) * SS + kt * 64 + sc;
        *(float4*)(p0)      = z4;
        *(float4*)(p0 + 4)  = z4;
        *(float4*)(p0 + 8)  = z4;
        *(float4*)(p0 + 12) = z4;
    }
}

// ---------------- launch ----------------
extern "C" void kernel_launch(void* const* d_in, const int* in_sizes, int n_in,
                              void* d_out, int out_size)
{
    const float* x  = (const float*)d_in[0];
    const float* Wq = (const float*)d_in[1];
    const float* bq = (const float*)d_in[2];
    const float* Wk = (const float*)d_in[3];
    const float* bk = (const float*)d_in[4];
    const float* Wv = (const float*)d_in[5];
    const float* bv = (const float*)d_in[6];
    const float* Wo = (const float*)d_in[7];
    const float* bo = (const float*)d_in[8];

    float* out  = (float*)d_out;
    float* attn = out + (size_t)NR * DD;   // tuple order: (out, attn)

    float *pW3, *pb3, *pQKV, *pC;
    cudaGetSymbolAddress((void**)&pW3,  g_W3);
    cudaGetSymbolAddress((void**)&pb3,  g_b3);
    cudaGetSymbolAddress((void**)&pQKV, g_QKV);
    cudaGetSymbolAddress((void**)&pC,   g_C);

    cudaFuncSetAttribute(fused_attn, cudaFuncAttributeMaxDynamicSharedMemorySize, SM_TOTAL);

    // 1) concat weights/biases
    concat_kernel<<<(DD * DD + 255) / 256, 256>>>(Wq, Wk, Wv, bq, bk, bv);

    // 2) fused QKV projection: (4096 x 3072) = x @ W3^T + b3   [tf32 tensor]
    gemm_nt_tf32<<<dim3(3072 / 128, NR / 128), 256>>>(x, pW3, pb3, pQKV, NR, 3072, DD);

    // 3+4+5) fused scores/softmax/ctx (+ writes attn output)
    fused_attn<<<dim3(SS / 64, BB * HH), 256, SM_TOTAL>>>(pQKV, attn, pC);

    // 6) output projection [tf32 tensor]
    gemm_nt_tf32<<<dim3(DD / 128, NR / 128), 256>>>(pC, Wo, bo, out, NR, DD, DD);
}

// round 4
// speedup vs baseline: 1.2077x; 1.2077x over previous
#include <cuda_runtime.h>
#include <stdint.h>

#define BB 2
#define SS 2048
#define DD 1024
#define HH 16
#define NR (BB*SS)            // 4096 rows
#define ATT_SCALE 0.125f      // 1/sqrt(64)

// ---------------- device scratch (no cudaMalloc allowed) ----------------
static __device__ float g_W3[3 * DD * DD];          // concat(Wq,Wk,Wv), tf32-rounded
static __device__ float g_Wo[DD * DD];              // Wo, tf32-rounded
static __device__ float g_b3[3 * DD];
static __device__ float g_X[(size_t)NR * DD];       // x, tf32-rounded
static __device__ float g_QKV[(size_t)NR * 3 * DD]; // (4096, 3072): Q|K|V (tf32-clean)
static __device__ float g_C[(size_t)NR * DD];       // ctx (B,S,D)   (tf32-clean)

// ---------------- tf32 / mma / cp.async helpers ----------------
__device__ __forceinline__ uint32_t f2t(float x) {
    uint32_t r;
    asm("cvt.rna.tf32.f32 %0, %1;" : "=r"(r) : "f"(x));
    return r;
}
__device__ __forceinline__ float f2tf(float x) { return __uint_as_float(f2t(x)); }

__device__ __forceinline__ void mma8(float* c, const uint32_t* a, const uint32_t* b) {
    asm volatile(
        "mma.sync.aligned.m16n8k8.row.col.f32.tf32.tf32.f32 "
        "{%0,%1,%2,%3},{%4,%5,%6,%7},{%8,%9},{%0,%1,%2,%3};"
        : "+f"(c[0]), "+f"(c[1]), "+f"(c[2]), "+f"(c[3])
        : "r"(a[0]), "r"(a[1]), "r"(a[2]), "r"(a[3]), "r"(b[0]), "r"(b[1]));
}
__device__ __forceinline__ void cp16(float* dst, const float* src) {
    uint32_t d = (uint32_t)__cvta_generic_to_shared(dst);
    asm volatile("cp.async.cg.shared.global [%0], [%1], 16;" :: "r"(d), "l"(src));
}
__device__ __forceinline__ void cp_commit() { asm volatile("cp.async.commit_group;"); }
template <int N>
__device__ __forceinline__ void cp_wait() { asm volatile("cp.async.wait_group %0;" :: "n"(N)); }

// ---------------- prep: concat + round weights; round x ----------------
__global__ void concat_kernel(const float* __restrict__ Wq, const float* __restrict__ Wk,
                              const float* __restrict__ Wv, const float* __restrict__ Wo,
                              const float* __restrict__ bq, const float* __restrict__ bk,
                              const float* __restrict__ bv) {
    int i = blockIdx.x * 256 + threadIdx.x;
    if (i < DD * DD) {
        g_W3[i]               = f2tf(Wq[i]);
        g_W3[DD * DD + i]     = f2tf(Wk[i]);
        g_W3[2 * DD * DD + i] = f2tf(Wv[i]);
        g_Wo[i]               = f2tf(Wo[i]);
    }
    if (i < DD) {
        g_b3[i]          = bq[i];
        g_b3[DD + i]     = bk[i];
        g_b3[2 * DD + i] = bv[i];
    }
}
__global__ void roundx_kernel(const float* __restrict__ x) {
    size_t i = (size_t)blockIdx.x * 256 + threadIdx.x;
    g_X[i] = f2tf(x[i]);
}

// ---------------- NT GEMM (tf32 tensor, cp.async 4-stage) ----------------
// C[M,N] = A[M,K] @ B[N,K]^T + bias.  A,B pre-rounded tf32-clean fp32.
// 128x128 tile, BK=16, 8 warps (4m x 2n), warp tile 32x64.
#define GSTG 2560   // 128*20 floats per stage per operand
template <bool RND>
__global__ __launch_bounds__(256, 2) void gemm_v3(
    const float* __restrict__ A, const float* __restrict__ Bw,
    const float* __restrict__ bias, float* __restrict__ C,
    int M, int N, int K)
{
    extern __shared__ float sm[];
    float* As = sm;               // [4][128][20]
    float* Bs = sm + 4 * GSTG;    // [4][128][20]

    const int t = threadIdx.x, lane = t & 31, w = t >> 5;
    const int g = lane >> 2, tg = lane & 3;
    const int wm = w & 3, wn = w >> 2;
    const int row0 = blockIdx.y * 128, col0 = blockIdx.x * 128;

    const int lrow = t >> 1, lseg = (t & 1) * 8;
    const float* Ap = A  + (size_t)(row0 + lrow) * K + lseg;
    const float* Bp = Bw + (size_t)(col0 + lrow) * K + lseg;
    float* Asd = As + lrow * 20 + lseg;
    float* Bsd = Bs + lrow * 20 + lseg;

    float acc[2][8][4];
#pragma unroll
    for (int i = 0; i < 2; i++)
#pragma unroll
        for (int j = 0; j < 8; j++)
#pragma unroll
            for (int q = 0; q < 4; q++) acc[i][j][q] = 0.f;

    const int nk = K / 16;
#pragma unroll
    for (int s = 0; s < 3; s++) {
        cp16(Asd + s * GSTG, Ap + s * 16);
        cp16(Asd + s * GSTG + 4, Ap + s * 16 + 4);
        cp16(Bsd + s * GSTG, Bp + s * 16);
        cp16(Bsd + s * GSTG + 4, Bp + s * 16 + 4);
        cp_commit();
    }

    for (int kc = 0; kc < nk; kc++) {
        cp_wait<2>();
        __syncthreads();
        if (kc + 3 < nk) {
            const int s = (kc + 3) & 3;
            const int k0 = (kc + 3) * 16;
            cp16(Asd + s * GSTG, Ap + k0);
            cp16(Asd + s * GSTG + 4, Ap + k0 + 4);
            cp16(Bsd + s * GSTG, Bp + k0);
            cp16(Bsd + s * GSTG + 4, Bp + k0 + 4);
        }
        cp_commit();

        const float* a = As + (kc & 3) * GSTG;
        const float* b = Bs + (kc & 3) * GSTG;
#pragma unroll
        for (int ks = 0; ks < 16; ks += 8) {
            uint32_t af[2][4], bf[8][2];
#pragma unroll
            for (int mt = 0; mt < 2; mt++) {
                const int r = wm * 32 + mt * 16 + g;
                af[mt][0] = __float_as_uint(a[r * 20 + ks + tg]);
                af[mt][1] = __float_as_uint(a[(r + 8) * 20 + ks + tg]);
                af[mt][2] = __float_as_uint(a[r * 20 + ks + tg + 4]);
                af[mt][3] = __float_as_uint(a[(r + 8) * 20 + ks + tg + 4]);
            }
#pragma unroll
            for (int nt = 0; nt < 8; nt++) {
                const int n = wn * 64 + nt * 8 + g;
                bf[nt][0] = __float_as_uint(b[n * 20 + ks + tg]);
                bf[nt][1] = __float_as_uint(b[n * 20 + ks + tg + 4]);
            }
#pragma unroll
            for (int mt = 0; mt < 2; mt++)
#pragma unroll
                for (int nt = 0; nt < 8; nt++)
                    mma8(acc[mt][nt], af[mt], bf[nt]);
        }
    }

#pragma unroll
    for (int mt = 0; mt < 2; mt++) {
        const int r = row0 + wm * 32 + mt * 16 + g;
#pragma unroll
        for (int nt = 0; nt < 8; nt++) {
            const int cc = col0 + wn * 64 + nt * 8 + 2 * tg;
            float2 v0, v1;
            v0.x = acc[mt][nt][0] + bias[cc];
            v0.y = acc[mt][nt][1] + bias[cc + 1];
            v1.x = acc[mt][nt][2] + bias[cc];
            v1.y = acc[mt][nt][3] + bias[cc + 1];
            if (RND) {
                v0.x = f2tf(v0.x); v0.y = f2tf(v0.y);
                v1.x = f2tf(v1.x); v1.y = f2tf(v1.y);
            }
            *(float2*)(C + (size_t)r * N + cc)       = v0;
            *(float2*)(C + (size_t)(r + 8) * N + cc) = v1;
        }
    }
}

// ---------------- scores: 128x128 tiles, one-shot K=64 ----------------
__global__ __launch_bounds__(256, 2) void scores_v3(
    const float* __restrict__ QKV, float* __restrict__ attn)
{
    const int kt = blockIdx.x, qt = blockIdx.y, z = blockIdx.z;
    if (kt > qt) return;
    const int b = z >> 4, h = z & 15;

    extern __shared__ float sm[];
    float* Qs = sm;               // [128][68]
    float* Ks = sm + 128 * 68;    // [128][68]

    const int t = threadIdx.x, lane = t & 31, w = t >> 5;
    const int g = lane >> 2, tg = lane & 3;
    const int wm = w & 3, wn = w >> 2;

    const int lrow = t >> 1, lseg = (t & 1) * 32;
    const float* Qp = QKV + ((size_t)(b * SS) + qt * 128 + lrow) * 3072 + h * 64 + lseg;
    const float* Kp = QKV + ((size_t)(b * SS) + kt * 128 + lrow) * 3072 + DD + h * 64 + lseg;
#pragma unroll
    for (int j = 0; j < 8; j++) {
        *(float4*)&Qs[lrow * 68 + lseg + j * 4] = *(const float4*)(Qp + j * 4);
        *(float4*)&Ks[lrow * 68 + lseg + j * 4] = *(const float4*)(Kp + j * 4);
    }
    __syncthreads();

    float acc[2][8][4];
#pragma unroll
    for (int i = 0; i < 2; i++)
#pragma unroll
        for (int j = 0; j < 8; j++)
#pragma unroll
            for (int q = 0; q < 4; q++) acc[i][j][q] = 0.f;

#pragma unroll
    for (int ks = 0; ks < 64; ks += 8) {
        uint32_t af[2][4], bf[8][2];
#pragma unroll
        for (int mt = 0; mt < 2; mt++) {
            const int r = wm * 32 + mt * 16 + g;
            af[mt][0] = __float_as_uint(Qs[r * 68 + ks + tg]);
            af[mt][1] = __float_as_uint(Qs[(r + 8) * 68 + ks + tg]);
            af[mt][2] = __float_as_uint(Qs[r * 68 + ks + tg + 4]);
            af[mt][3] = __float_as_uint(Qs[(r + 8) * 68 + ks + tg + 4]);
        }
#pragma unroll
        for (int nt = 0; nt < 8; nt++) {
            const int n = wn * 64 + nt * 8 + g;
            bf[nt][0] = __float_as_uint(Ks[n * 68 + ks + tg]);
            bf[nt][1] = __float_as_uint(Ks[n * 68 + ks + tg + 4]);
        }
#pragma unroll
        for (int mt = 0; mt < 2; mt++)
#pragma unroll
            for (int nt = 0; nt < 8; nt++)
                mma8(acc[mt][nt], af[mt], bf[nt]);
    }

#pragma unroll
    for (int mt = 0; mt < 2; mt++) {
        const int r = qt * 128 + wm * 32 + mt * 16 + g;
#pragma unroll
        for (int nt = 0; nt < 8; nt++) {
            const int cc = kt * 128 + wn * 64 + nt * 8 + 2 * tg;
            float2 v0, v1;
            v0.x = acc[mt][nt][0] * ATT_SCALE; v0.y = acc[mt][nt][1] * ATT_SCALE;
            v1.x = acc[mt][nt][2] * ATT_SCALE; v1.y = acc[mt][nt][3] * ATT_SCALE;
            *(float2*)(attn + ((size_t)z * SS + r) * SS + cc)       = v0;
            *(float2*)(attn + ((size_t)z * SS + r + 8) * SS + cc)   = v1;
        }
    }
}

// ---------------- row softmax with causal mask (writes zeros above diag) ----------
__global__ __launch_bounds__(256) void softmax_kernel(float* __restrict__ attn)
{
    const size_t row = blockIdx.x;           // row = z*S + q
    const int q = (int)(row & (SS - 1));
    float* p = attn + row * (size_t)SS;
    const int t = threadIdx.x;

    float v[8];
    float m = -1e30f;
#pragma unroll
    for (int l = 0; l < 8; l++) {
        const int i = t + l * 256;
        v[l] = (i <= q) ? p[i] : -1e30f;
        m = fmaxf(m, v[l]);
    }
#pragma unroll
    for (int o = 16; o > 0; o >>= 1) m = fmaxf(m, __shfl_xor_sync(0xffffffffu, m, o));
    __shared__ float redm[8];
    __shared__ float reds[8];
    if ((t & 31) == 0) redm[t >> 5] = m;
    __syncthreads();
    float bm = redm[0];
#pragma unroll
    for (int w = 1; w < 8; w++) bm = fmaxf(bm, redm[w]);

    float s = 0.f;
#pragma unroll
    for (int l = 0; l < 8; l++) {
        const int i = t + l * 256;
        v[l] = (i <= q) ? __expf(v[l] - bm) : 0.f;
        s += v[l];
    }
#pragma unroll
    for (int o = 16; o > 0; o >>= 1) s += __shfl_xor_sync(0xffffffffu, s, o);
    if ((t & 31) == 0) reds[t >> 5] = s;
    __syncthreads();
    float tot = 0.f;
#pragma unroll
    for (int w = 0; w < 8; w++) tot += reds[w];
    const float inv = 1.0f / tot;
#pragma unroll
    for (int l = 0; l < 8; l++) {
        const int i = t + l * 256;
        p[i] = v[l] * inv;
    }
}

// ---------------- ctx = attn @ V, 128q x 64d tiles, 2-stage cp.async ----------
#define PSTG (128*68)
#define VSTG (64*72)
__global__ __launch_bounds__(256, 2) void ctx_v3(
    const float* __restrict__ attn, const float* __restrict__ QKV,
    float* __restrict__ Cout)
{
    extern __shared__ float sm[];
    float* Ps = sm;                 // [2][128][68]
    float* Vs = sm + 2 * PSTG;      // [2][64][72]

    const int qt = 15 - blockIdx.x;       // reversed: longest blocks first
    const int z = blockIdx.y;
    const int b = z >> 4, h = z & 15;
    const int t = threadIdx.x, lane = t & 31, w = t >> 5;
    const int g = lane >> 2, tg = lane & 3;
    const int wm = w & 3, wn = w >> 2;

    const int prow = t >> 1, pseg = (t & 1) * 32;
    const int vrow = t >> 2, vseg = (t & 3) * 16;
    const float* Pp = attn + ((size_t)z * SS + qt * 128 + prow) * SS + pseg;
    const float* Vp = QKV + ((size_t)(b * SS) + vrow) * 3072 + 2 * DD + h * 64 + vseg;
    float* Psd = Ps + prow * 68 + pseg;
    float* Vsd = Vs + vrow * 72 + vseg;

    const int cnt = 2 * qt + 2;

    float acc[2][4][4];
#pragma unroll
    for (int i = 0; i < 2; i++)
#pragma unroll
        for (int j = 0; j < 4; j++)
#pragma unroll
            for (int q = 0; q < 4; q++) acc[i][j][q] = 0.f;

    // prologue: stage 0 = kt 0
    {
#pragma unroll
        for (int j = 0; j < 8; j++) cp16(Psd + j * 4, Pp + j * 4);
#pragma unroll
        for (int j = 0; j < 4; j++) cp16(Vsd + j * 4, Vp + j * 4);
        cp_commit();
    }

    for (int kti = 0; kti < cnt; kti++) {
        if (kti + 1 < cnt) {
            const int st = (kti + 1) & 1;
#pragma unroll
            for (int j = 0; j < 8; j++)
                cp16(Psd + st * PSTG + j * 4, Pp + (kti + 1) * 64 + j * 4);
#pragma unroll
            for (int j = 0; j < 4; j++)
                cp16(Vsd + st * VSTG + j * 4, Vp + (size_t)(kti + 1) * 64 * 3072 + j * 4);
        }
        cp_commit();
        cp_wait<1>();
        __syncthreads();

        const float* pp = Ps + (kti & 1) * PSTG;
        const float* vv = Vs + (kti & 1) * VSTG;
#pragma unroll
        for (int ks = 0; ks < 64; ks += 8) {
            uint32_t af[2][4], bf[4][2];
#pragma unroll
            for (int mt = 0; mt < 2; mt++) {
                const int r = wm * 32 + mt * 16 + g;
                af[mt][0] = f2t(pp[r * 68 + ks + tg]);
                af[mt][1] = f2t(pp[(r + 8) * 68 + ks + tg]);
                af[mt][2] = f2t(pp[r * 68 + ks + tg + 4]);
                af[mt][3] = f2t(pp[(r + 8) * 68 + ks + tg + 4]);
            }
#pragma unroll
            for (int nt = 0; nt < 4; nt++) {
                const int n = wn * 32 + nt * 8 + g;
                bf[nt][0] = __float_as_uint(vv[(ks + tg) * 72 + n]);
                bf[nt][1] = __float_as_uint(vv[(ks + tg + 4) * 72 + n]);
            }
#pragma unroll
            for (int mt = 0; mt < 2; mt++)
#pragma unroll
                for (int nt = 0; nt < 4; nt++)
                    mma8(acc[mt][nt], af[mt], bf[nt]);
        }
        __syncthreads();
    }

#pragma unroll
    for (int mt = 0; mt < 2; mt++) {
        const int qrow = qt * 128 + wm * 32 + mt * 16 + g;
#pragma unroll
        for (int nt = 0; nt < 4; nt++) {
            const int cc = h * 64 + wn * 32 + nt * 8 + 2 * tg;
            float2 v0, v1;
            v0.x = f2tf(acc[mt][nt][0]); v0.y = f2tf(acc[mt][nt][1]);
            v1.x = f2tf(acc[mt][nt][2]); v1.y = f2tf(acc[mt][nt][3]);
            *(float2*)(Cout + ((size_t)(b * SS) + qrow) * DD + cc)     = v0;
            *(float2*)(Cout + ((size_t)(b * SS) + qrow + 8) * DD + cc) = v1;
        }
    }
}

// ---------------- launch ----------------
extern "C" void kernel_launch(void* const* d_in, const int* in_sizes, int n_in,
                              void* d_out, int out_size)
{
    const float* x  = (const float*)d_in[0];
    const float* Wq = (const float*)d_in[1];
    const float* bq = (const float*)d_in[2];
    const float* Wk = (const float*)d_in[3];
    const float* bk = (const float*)d_in[4];
    const float* Wv = (const float*)d_in[5];
    const float* bv = (const float*)d_in[6];
    const float* Wo = (const float*)d_in[7];
    const float* bo = (const float*)d_in[8];

    float* out  = (float*)d_out;
    float* attn = out + (size_t)NR * DD;   // tuple order: (out, attn)

    float *pW3, *pWo, *pb3, *pX, *pQKV, *pC;
    cudaGetSymbolAddress((void**)&pW3,  g_W3);
    cudaGetSymbolAddress((void**)&pWo,  g_Wo);
    cudaGetSymbolAddress((void**)&pb3,  g_b3);
    cudaGetSymbolAddress((void**)&pX,   g_X);
    cudaGetSymbolAddress((void**)&pQKV, g_QKV);
    cudaGetSymbolAddress((void**)&pC,   g_C);

    const int gemm_smem   = 4 * GSTG * 2 * 4;            // 81920
    const int scores_smem = 2 * 128 * 68 * 4;            // 69632
    const int ctx_smem    = (2 * PSTG + 2 * VSTG) * 4;   // 106496
    cudaFuncSetAttribute(gemm_v3<true>,  cudaFuncAttributeMaxDynamicSharedMemorySize, gemm_smem);
    cudaFuncSetAttribute(gemm_v3<false>, cudaFuncAttributeMaxDynamicSharedMemorySize, gemm_smem);
    cudaFuncSetAttribute(scores_v3,      cudaFuncAttributeMaxDynamicSharedMemorySize, scores_smem);
    cudaFuncSetAttribute(ctx_v3,         cudaFuncAttributeMaxDynamicSharedMemorySize, ctx_smem);

    // 1) prep: concat+round weights, round x
    concat_kernel<<<(DD * DD + 255) / 256, 256>>>(Wq, Wk, Wv, Wo, bq, bk, bv);
    roundx_kernel<<<(NR * DD) / 256, 256>>>(x);

    // 2) fused QKV projection (stores tf32-rounded outputs)
    gemm_v3<true><<<dim3(3072 / 128, NR / 128), 256, gemm_smem>>>(pX, pW3, pb3, pQKV, NR, 3072, DD);

    // 3) raw causal scores into attn region
    scores_v3<<<dim3(SS / 128, SS / 128, BB * HH), 256, scores_smem>>>(pQKV, attn);

    // 4) softmax per row (also zero-fills masked region)
    softmax_kernel<<<BB * HH * SS, 256>>>(attn);

    // 5) ctx = attn @ V (stores tf32-rounded ctx)
    ctx_v3<<<dim3(SS / 128, BB * HH), 256, ctx_smem>>>(attn, pQKV, pC);

    // 6) output projection (exact fp32 epilogue)
    gemm_v3<false><<<dim3(DD / 128, NR / 128), 256, gemm_smem>>>(pC, pWo, bo, out, NR, DD, DD);
}